// round 2
// baseline (speedup 1.0000x reference)
#include <cuda_runtime.h>
#include <math.h>

// ---------------- problem constants ----------------
#define NN    883          // nodes
#define NP    896          // padded row length for S (zero-padded cols)
#define TT    12           // timesteps
#define BB    64           // batch
#define B2    128          // batch * 2 directions
#define DOUTC 64           // hidden dim
#define DE    10           // embedding dim
#define KI    132          // K-dim of per-node GEMMs: 2 (cheb) * 66 (DI)
#define HCOLS 8192         // B2 * DOUTC
#define XCOLS 1536         // TT * BB * 2

// ---------------- device scratch (static, no allocs) ----------------
__device__ float d_S[(size_t)NN * NP];          // S = softmax(relu(EE^T)) + adj, zero-padded cols
__device__ float d_xr[(size_t)NN * XCOLS];      // x reordered: [m][(t*B+b)*2+i]
__device__ float d_SX[(size_t)NN * XCOLS];      // S @ xr
__device__ float d_h[(size_t)NN * HCOLS];       // h state: [n][b2][c]
__device__ float d_Sh[(size_t)NN * HCOLS];      // S @ h
__device__ float d_rh[(size_t)NN * HCOLS];      // r * h
__device__ float d_Srh[(size_t)NN * HCOLS];     // S @ (r*h)
__device__ float d_z[(size_t)NN * HCOLS];       // update gate z
__device__ float d_Wgn[(size_t)2 * NN * KI * 128];  // per-node gate weights
__device__ float d_bgn[(size_t)2 * NN * 128];
__device__ float d_Wcn[(size_t)2 * NN * KI * 64];   // per-node candidate weights
__device__ float d_bcn[(size_t)2 * NN * 64];

// ---------------- kernel: S = softmax(relu(E E^T)) + adj ----------------
__global__ void compute_S_kernel(const float* __restrict__ E, const float* __restrict__ adj) {
    __shared__ float sc[NN];
    __shared__ float red[256];
    int n = blockIdx.x;
    int tid = threadIdx.x;
    float en[DE];
#pragma unroll
    for (int d = 0; d < DE; d++) en[d] = E[n * DE + d];
    float lmax = 0.0f;  // relu output >= 0
    for (int m = tid; m < NN; m += 256) {
        float s = 0.f;
#pragma unroll
        for (int d = 0; d < DE; d++) s += en[d] * E[m * DE + d];
        s = fmaxf(s, 0.f);
        sc[m] = s;
        lmax = fmaxf(lmax, s);
    }
    red[tid] = lmax;
    __syncthreads();
    for (int s = 128; s > 0; s >>= 1) {
        if (tid < s) red[tid] = fmaxf(red[tid], red[tid + s]);
        __syncthreads();
    }
    float mx = red[0];
    __syncthreads();
    float lsum = 0.f;
    for (int m = tid; m < NN; m += 256) {
        float e = expf(sc[m] - mx);
        sc[m] = e;
        lsum += e;
    }
    red[tid] = lsum;
    __syncthreads();
    for (int s = 128; s > 0; s >>= 1) {
        if (tid < s) red[tid] += red[tid + s];
        __syncthreads();
    }
    float inv = 1.0f / red[0];
    for (int m = tid; m < NP; m += 256) {
        float v = 0.f;
        if (m < NN) v = sc[m] * inv + adj[(size_t)n * NN + m];
        d_S[(size_t)n * NP + m] = v;
    }
}

// ---------------- kernel: reorder x -> [m][(t*B+b)*2+i] ----------------
__global__ void reorder_x_kernel(const float* __restrict__ x) {
    int idx = blockIdx.x * blockDim.x + threadIdx.x;
    if (idx >= NN * XCOLS) return;
    int m = idx / XCOLS;
    int c = idx - m * XCOLS;
    int i = c & 1;
    int tb = c >> 1;
    int t = tb / BB;
    int b = tb - t * BB;
    d_xr[idx] = x[(((size_t)b * TT + t) * NN + m) * 2 + i];
}

// ---------------- generic SGEMM: C[883 x ncols] = S(883x883) * B(883 x ncols) ----------------
// 128x128 tile, BK=16, 8x8 per thread, 256 threads.
__device__ __forceinline__ void sgemm_body(const float* __restrict__ Bmat,
                                           float* __restrict__ C, int ncols) {
    __shared__ float As[16][132];   // transposed S tile [k][m], padded
    __shared__ float Bs[16][128];
    const int tid = threadIdx.x;
    const int m0 = blockIdx.y * 128;
    const int n0 = blockIdx.x * 128;
    const int tx = tid & 15;
    const int ty = tid >> 4;
    const int aRow = tid >> 2;       // 0..63
    const int ak = (tid & 3) * 4;    // 0,4,8,12
    const int bCol = (tid & 31) * 4; // 0..124
    const int bRow = tid >> 5;       // 0..7
    float acc[8][8];
#pragma unroll
    for (int i = 0; i < 8; i++)
#pragma unroll
        for (int j = 0; j < 8; j++) acc[i][j] = 0.f;

    for (int k0 = 0; k0 < NN; k0 += 16) {
#pragma unroll
        for (int r = 0; r < 2; r++) {
            int m = m0 + aRow + r * 64;
            float4 v = make_float4(0.f, 0.f, 0.f, 0.f);
            if (m < NN) v = *(const float4*)&d_S[(size_t)m * NP + k0 + ak];  // padded cols are 0
            As[ak + 0][aRow + r * 64] = v.x;
            As[ak + 1][aRow + r * 64] = v.y;
            As[ak + 2][aRow + r * 64] = v.z;
            As[ak + 3][aRow + r * 64] = v.w;
        }
#pragma unroll
        for (int r = 0; r < 2; r++) {
            int k = k0 + bRow + r * 8;
            float4 v = make_float4(0.f, 0.f, 0.f, 0.f);
            if (k < NN) v = *(const float4*)&Bmat[(size_t)k * ncols + n0 + bCol];
            *(float4*)&Bs[bRow + r * 8][bCol] = v;
        }
        __syncthreads();
#pragma unroll
        for (int k = 0; k < 16; k++) {
            float a[8], b[8];
#pragma unroll
            for (int i = 0; i < 4; i++) {
                a[i] = As[k][ty * 4 + i];
                a[i + 4] = As[k][64 + ty * 4 + i];
            }
#pragma unroll
            for (int j = 0; j < 4; j++) {
                b[j] = Bs[k][tx * 4 + j];
                b[j + 4] = Bs[k][64 + tx * 4 + j];
            }
#pragma unroll
            for (int i = 0; i < 8; i++)
#pragma unroll
                for (int j = 0; j < 8; j++) acc[i][j] += a[i] * b[j];
        }
        __syncthreads();
    }
#pragma unroll
    for (int i = 0; i < 8; i++) {
        int m = m0 + (i < 4 ? ty * 4 + i : 64 + ty * 4 + (i - 4));
        if (m >= NN) continue;
#pragma unroll
        for (int j = 0; j < 8; j++) {
            int c = n0 + (j < 4 ? tx * 4 + j : 64 + tx * 4 + (j - 4));
            C[(size_t)m * ncols + c] = acc[i][j];
        }
    }
}

__global__ void sgemm_SX_kernel() { sgemm_body(d_xr, d_SX, XCOLS); }
__global__ void sgemm_Sh_kernel() { sgemm_body(d_h, d_Sh, HCOLS); }
__global__ void sgemm_Srh_kernel() { sgemm_body(d_rh, d_Srh, HCOLS); }

// ---------------- per-node weight materialization: Wn = E[n] . W ----------------
__global__ void prep_gate_kernel(const float* __restrict__ E,
                                 const float* __restrict__ Wf, const float* __restrict__ bf,
                                 const float* __restrict__ Wb, const float* __restrict__ bb) {
    int n = blockIdx.x, dir = blockIdx.y;
    const float* W = dir ? Wb : Wf;
    const float* bsrc = dir ? bb : bf;
    __shared__ float en[DE];
    if (threadIdx.x < DE) en[threadIdx.x] = E[n * DE + threadIdx.x];
    __syncthreads();
    float* Wo = &d_Wgn[((size_t)dir * NN + n) * (KI * 128)];
    for (int e = threadIdx.x; e < KI * 128; e += blockDim.x) {
        float s = 0.f;
#pragma unroll
        for (int d = 0; d < DE; d++) s += en[d] * W[(size_t)d * (KI * 128) + e];
        Wo[e] = s;
    }
    for (int o = threadIdx.x; o < 128; o += blockDim.x) {
        float s = 0.f;
#pragma unroll
        for (int d = 0; d < DE; d++) s += en[d] * bsrc[d * 128 + o];
        d_bgn[((size_t)dir * NN + n) * 128 + o] = s;
    }
}

__global__ void prep_cand_kernel(const float* __restrict__ E,
                                 const float* __restrict__ Wf, const float* __restrict__ bf,
                                 const float* __restrict__ Wb, const float* __restrict__ bb) {
    int n = blockIdx.x, dir = blockIdx.y;
    const float* W = dir ? Wb : Wf;
    const float* bsrc = dir ? bb : bf;
    __shared__ float en[DE];
    if (threadIdx.x < DE) en[threadIdx.x] = E[n * DE + threadIdx.x];
    __syncthreads();
    float* Wo = &d_Wcn[((size_t)dir * NN + n) * (KI * 64)];
    for (int e = threadIdx.x; e < KI * 64; e += blockDim.x) {
        float s = 0.f;
#pragma unroll
        for (int d = 0; d < DE; d++) s += en[d] * W[(size_t)d * (KI * 64) + e];
        Wo[e] = s;
    }
    for (int o = threadIdx.x; o < 64; o += blockDim.x) {
        float s = 0.f;
#pragma unroll
        for (int d = 0; d < DE; d++) s += en[d] * bsrc[d * 64 + o];
        d_bcn[((size_t)dir * NN + n) * 64 + o] = s;
    }
}

__global__ void zero_h_kernel() {
    int idx = blockIdx.x * blockDim.x + threadIdx.x;
    if (idx < NN * HCOLS) d_h[idx] = 0.f;
}

// ---------------- gate: zr = sigmoid(A[64x132] @ Wg_n[132x128] + b); z, r*h ----------------
__global__ void gate_kernel(const float* __restrict__ x, int t) {
    extern __shared__ float sm[];
    float(*As)[133] = (float(*)[133])sm;        // [64][133]
    float* Ws = sm + 64 * 133;                  // [KI][128]
    int n = blockIdx.x, dir = blockIdx.y;
    int t_eff = dir ? (TT - 1 - t) : t;
    int tid = threadIdx.x;

    for (int e = tid; e < 64 * KI; e += 256) {
        int b = e / KI;
        int i = e - b * KI;
        int b2 = dir * 64 + b;
        float v;
        if (i < 2)       v = x[(((size_t)b * TT + t_eff) * NN + n) * 2 + i];
        else if (i < 66) v = d_h[((size_t)n * B2 + b2) * DOUTC + (i - 2)];
        else if (i < 68) v = d_SX[(size_t)n * XCOLS + (t_eff * BB + b) * 2 + (i - 66)];
        else             v = d_Sh[((size_t)n * B2 + b2) * DOUTC + (i - 68)];
        As[b][i] = v;
    }
    {
        const float* Wsrc = &d_Wgn[((size_t)dir * NN + n) * (KI * 128)];
        for (int e = tid; e < KI * 128; e += 256) Ws[e] = Wsrc[e];
    }
    __syncthreads();

    int tx = tid & 15, ty = tid >> 4;
    float acc[4][8];
#pragma unroll
    for (int i = 0; i < 4; i++)
#pragma unroll
        for (int j = 0; j < 8; j++) acc[i][j] = 0.f;

    for (int k = 0; k < KI; k++) {
        float a[4], w[8];
#pragma unroll
        for (int i = 0; i < 4; i++) a[i] = As[ty + 16 * i][k];
#pragma unroll
        for (int j = 0; j < 8; j++) w[j] = Ws[k * 128 + tx + 16 * j];
#pragma unroll
        for (int i = 0; i < 4; i++)
#pragma unroll
            for (int j = 0; j < 8; j++) acc[i][j] += a[i] * w[j];
    }

    const float* bgn = &d_bgn[((size_t)dir * NN + n) * 128];
#pragma unroll
    for (int i = 0; i < 4; i++) {
        int b = ty + 16 * i;
        int b2 = dir * 64 + b;
        size_t hb = ((size_t)n * B2 + b2) * DOUTC;
#pragma unroll
        for (int j = 0; j < 8; j++) {
            int o = tx + 16 * j;
            float v = acc[i][j] + bgn[o];
            float s = 1.f / (1.f + expf(-v));
            if (o < DOUTC) d_z[hb + o] = s;
            else           d_rh[hb + (o - DOUTC)] = s * d_h[hb + (o - DOUTC)];
        }
    }
}

// ---------------- candidate + state update + output write ----------------
__global__ void cand_kernel(const float* __restrict__ x, float* __restrict__ out, int t) {
    extern __shared__ float sm[];
    float(*As)[133] = (float(*)[133])sm;        // [64][133]
    float* Ws = sm + 64 * 133;                  // [KI][64]
    int n = blockIdx.x, dir = blockIdx.y;
    int t_eff = dir ? (TT - 1 - t) : t;
    int tid = threadIdx.x;

    for (int e = tid; e < 64 * KI; e += 256) {
        int b = e / KI;
        int i = e - b * KI;
        int b2 = dir * 64 + b;
        float v;
        if (i < 2)       v = x[(((size_t)b * TT + t_eff) * NN + n) * 2 + i];
        else if (i < 66) v = d_rh[((size_t)n * B2 + b2) * DOUTC + (i - 2)];
        else if (i < 68) v = d_SX[(size_t)n * XCOLS + (t_eff * BB + b) * 2 + (i - 66)];
        else             v = d_Srh[((size_t)n * B2 + b2) * DOUTC + (i - 68)];
        As[b][i] = v;
    }
    {
        const float* Wsrc = &d_Wcn[((size_t)dir * NN + n) * (KI * 64)];
        for (int e = tid; e < KI * 64; e += 256) Ws[e] = Wsrc[e];
    }
    __syncthreads();

    int tx = tid & 15, ty = tid >> 4;
    float acc[4][4];
#pragma unroll
    for (int i = 0; i < 4; i++)
#pragma unroll
        for (int j = 0; j < 4; j++) acc[i][j] = 0.f;

    for (int k = 0; k < KI; k++) {
        float a[4], w[4];
#pragma unroll
        for (int i = 0; i < 4; i++) a[i] = As[ty + 16 * i][k];
#pragma unroll
        for (int j = 0; j < 4; j++) w[j] = Ws[k * 64 + tx + 16 * j];
#pragma unroll
        for (int i = 0; i < 4; i++)
#pragma unroll
            for (int j = 0; j < 4; j++) acc[i][j] += a[i] * w[j];
    }

    const float* bcn = &d_bcn[((size_t)dir * NN + n) * 64];
#pragma unroll
    for (int i = 0; i < 4; i++) {
        int b = ty + 16 * i;
        int b2 = dir * 64 + b;
        size_t hb = ((size_t)n * B2 + b2) * DOUTC;
#pragma unroll
        for (int j = 0; j < 4; j++) {
            int o = tx + 16 * j;
            float hc = tanhf(acc[i][j] + bcn[o]);
            float hold = d_h[hb + o];
            float z = d_z[hb + o];
            float hn = z * hold + (1.f - z) * hc;
            d_h[hb + o] = hn;
            out[(((size_t)b * TT + t) * NN + n) * 128 + dir * DOUTC + o] = hn;
        }
    }
}

// ---------------- launch ----------------
extern "C" void kernel_launch(void* const* d_in, const int* in_sizes, int n_in,
                              void* d_out, int out_size) {
    const float* x    = (const float*)d_in[0];
    const float* adj  = (const float*)d_in[1];
    const float* E    = (const float*)d_in[2];
    const float* Wg_f = (const float*)d_in[3];
    const float* bg_f = (const float*)d_in[4];
    const float* Wc_f = (const float*)d_in[5];
    const float* bc_f = (const float*)d_in[6];
    const float* Wg_b = (const float*)d_in[7];
    const float* bg_b = (const float*)d_in[8];
    const float* Wc_b = (const float*)d_in[9];
    const float* bc_b = (const float*)d_in[10];
    float* out = (float*)d_out;

    const int gate_smem = (64 * 133 + KI * 128) * (int)sizeof(float);  // ~101.6 KB
    const int cand_smem = (64 * 133 + KI * 64) * (int)sizeof(float);   // ~67.8 KB
    cudaFuncSetAttribute(gate_kernel, cudaFuncAttributeMaxDynamicSharedMemorySize, gate_smem);
    cudaFuncSetAttribute(cand_kernel, cudaFuncAttributeMaxDynamicSharedMemorySize, cand_smem);

    compute_S_kernel<<<NN, 256>>>(E, adj);
    reorder_x_kernel<<<(NN * XCOLS + 255) / 256, 256>>>(x);
    sgemm_SX_kernel<<<dim3(XCOLS / 128, 7), 256>>>();
    prep_gate_kernel<<<dim3(NN, 2), 256>>>(E, Wg_f, bg_f, Wg_b, bg_b);
    prep_cand_kernel<<<dim3(NN, 2), 256>>>(E, Wc_f, bc_f, Wc_b, bc_b);
    zero_h_kernel<<<(NN * HCOLS + 1023) / 1024, 1024>>>();

    for (int t = 0; t < TT; t++) {
        sgemm_Sh_kernel<<<dim3(HCOLS / 128, 7), 256>>>();
        gate_kernel<<<dim3(NN, 2), 256, gate_smem>>>(x, t);
        sgemm_Srh_kernel<<<dim3(HCOLS / 128, 7), 256>>>();
        cand_kernel<<<dim3(NN, 2), 256, cand_smem>>>(x, out, t);
    }
}

// round 4
// speedup vs baseline: 1.2072x; 1.2072x over previous
#include <cuda_runtime.h>
#include <math.h>
#include <stdint.h>

// ---------------- problem constants ----------------
#define NN    883          // nodes
#define KP    896          // padded node dim
#define TT    12           // timesteps
#define BB    64           // batch
#define B2    128          // batch * 2 directions
#define DOUTC 64           // hidden dim
#define DE    10           // embedding dim
#define KI    132          // K-dim of per-node GEMMs: 2 (cheb) * 66 (DI)
#define HCOLS 8192         // B2 * DOUTC
#define XCOLS 1536         // TT * BB * 2
#define BK    16
#define KCH   56           // 896 / 16

// ---------------- device scratch (static, no allocs) ----------------
__device__ float d_S[(size_t)KP * KP];          // S = softmax(relu(EE^T)) + adj, zero-padded
__device__ float d_xr[(size_t)NN * XCOLS];      // x reordered: [m][(t*B+b)*2+i]
__device__ float d_SX[(size_t)NN * XCOLS];      // S @ xr
__device__ float d_h[(size_t)NN * HCOLS];       // h state: [n][b2][c]
__device__ float d_Sh[(size_t)NN * HCOLS];      // S @ h
__device__ float d_rh[(size_t)NN * HCOLS];      // r * h
__device__ float d_Srh[(size_t)NN * HCOLS];     // S @ (r*h)
__device__ float d_z[(size_t)NN * HCOLS];       // update gate z
__device__ float d_Wgn[(size_t)2 * NN * KI * 128];
__device__ float d_bgn[(size_t)2 * NN * 128];
__device__ float d_Wcn[(size_t)2 * NN * KI * 64];
__device__ float d_bcn[(size_t)2 * NN * 64];

// ---------------- helpers ----------------
__device__ __forceinline__ uint32_t smem_u32(const void* p) {
    return (uint32_t)__cvta_generic_to_shared(p);
}
__device__ __forceinline__ void cpa16(uint32_t dst, const float* src) {
    asm volatile("cp.async.cg.shared.global [%0], [%1], 16;" :: "r"(dst), "l"(src));
}
__device__ __forceinline__ void cpa16z(uint32_t dst, const float* src, int srcsize) {
    asm volatile("cp.async.cg.shared.global [%0], [%1], 16, %2;"
                 :: "r"(dst), "l"(src), "r"(srcsize));
}
__device__ __forceinline__ void split_tf32(float v, uint32_t& hi, uint32_t& lo) {
    uint32_t h = __float_as_uint(v) & 0xffffe000u;
    hi = h;
    lo = __float_as_uint(v - __uint_as_float(h));
}
#define MMA_TF32(d, a, b)                                                      \
    asm volatile("mma.sync.aligned.m16n8k8.row.col.f32.tf32.tf32.f32 "         \
                 "{%0,%1,%2,%3}, {%4,%5,%6,%7}, {%8,%9}, {%0,%1,%2,%3};"       \
                 : "+f"((d)[0]), "+f"((d)[1]), "+f"((d)[2]), "+f"((d)[3])       \
                 : "r"((a)[0]), "r"((a)[1]), "r"((a)[2]), "r"((a)[3]),          \
                   "r"((b)[0]), "r"((b)[1]))

// ---------------- kernel: S = softmax(relu(E E^T)) + adj, padded to [KP][KP] ----------------
__global__ void compute_S_kernel(const float* __restrict__ E, const float* __restrict__ adj) {
    __shared__ float sc[NN];
    __shared__ float red[256];
    int n = blockIdx.x;
    int tid = threadIdx.x;
    if (n >= NN) {
        for (int m = tid; m < KP; m += 256) d_S[(size_t)n * KP + m] = 0.f;
        return;
    }
    float en[DE];
#pragma unroll
    for (int d = 0; d < DE; d++) en[d] = E[n * DE + d];
    float lmax = 0.0f;
    for (int m = tid; m < NN; m += 256) {
        float s = 0.f;
#pragma unroll
        for (int d = 0; d < DE; d++) s += en[d] * E[m * DE + d];
        s = fmaxf(s, 0.f);
        sc[m] = s;
        lmax = fmaxf(lmax, s);
    }
    red[tid] = lmax;
    __syncthreads();
    for (int s = 128; s > 0; s >>= 1) {
        if (tid < s) red[tid] = fmaxf(red[tid], red[tid + s]);
        __syncthreads();
    }
    float mx = red[0];
    __syncthreads();
    float lsum = 0.f;
    for (int m = tid; m < NN; m += 256) {
        float e = expf(sc[m] - mx);
        sc[m] = e;
        lsum += e;
    }
    red[tid] = lsum;
    __syncthreads();
    for (int s = 128; s > 0; s >>= 1) {
        if (tid < s) red[tid] += red[tid + s];
        __syncthreads();
    }
    float inv = 1.0f / red[0];
    for (int m = tid; m < KP; m += 256) {
        float v = (m < NN) ? (sc[m] * inv + adj[(size_t)n * NN + m]) : 0.f;
        d_S[(size_t)n * KP + m] = v;
    }
}

// ---------------- kernel: reorder x -> [m][(t*B+b)*2+i] ----------------
__global__ void reorder_x_kernel(const float* __restrict__ x) {
    int idx = blockIdx.x * blockDim.x + threadIdx.x;
    if (idx >= NN * XCOLS) return;
    int m = idx / XCOLS;
    int c = idx - m * XCOLS;
    int i = c & 1;
    int tb = c >> 1;
    int t = tb / BB;
    int b = tb - t * BB;
    d_xr[idx] = x[(((size_t)b * TT + t) * NN + m) * 2 + i];
}

// ---------------- tf32 3-split mma.sync GEMM: C[883 x ncols] = S @ B ----------------
// A = d_S [KP x KP] (zero padded).  B = Bsrc [NN x ncols] row-major (k-major).
// CTA tile 128x128, BK=16, 8 warps as 4(M) x 2(N), warp tile 32x64, m16n8k8.
__global__ void __launch_bounds__(256)
gemm_mma_kernel(const float* __restrict__ Bsrc, float* __restrict__ C, int ncols) {
    __shared__ float As[2][128][20];   // [stage][m][k], stride 20 (conflict-free frags)
    __shared__ float Bs[2][16][136];   // [stage][k][n], stride 136

    const int tid = threadIdx.x;
    const int wid = tid >> 5;
    const int lane = tid & 31;
    const int gid = lane >> 2;   // 0..7
    const int tig = lane & 3;    // 0..3
    const int m0 = blockIdx.y * 128;
    const int n0 = blockIdx.x * 128;
    const int wm = (wid & 3) * 32;
    const int wn = (wid >> 2) * 64;

    float acc[2][8][4];
#pragma unroll
    for (int tm = 0; tm < 2; tm++)
#pragma unroll
        for (int j = 0; j < 8; j++)
#pragma unroll
            for (int q = 0; q < 4; q++) acc[tm][j][q] = 0.f;

    // load task decomposition (2 x 16B per thread for each of A and B)
    const int aR = tid >> 1;                 // row 0..127
    const int aC = (tid & 1) * 8;            // two 16B chunks cover 16 floats
    const int bR = tid >> 4;                 // k row 0..15
    const int bC = (tid & 15) * 8;           // two 16B chunks cover... (see below)

    // A: 128 rows x 16 floats = 128 rows x 2 chunks-of-8 -> 256 tasks of 32B? use 2x16B:
    //   thread handles row aR, floats [aC, aC+4) and [aC+4, aC+8)? simpler: 2 cp.async.
    // B: 16 rows x 128 floats = 16 x 8 chunks-of-16 floats; thread handles row bR,
    //   floats [bC, bC+4) and [bC+4, bC+8).

#define LOAD_STAGE(s, k0)                                                                \
    do {                                                                                 \
        const float* asrc = &d_S[(size_t)(m0 + aR) * KP + (k0) + aC];                    \
        uint32_t adst = smem_u32(&As[s][aR][aC]);                                        \
        cpa16(adst, asrc);                                                               \
        cpa16(adst + 16u, asrc + 4);                                                     \
        int kk = (k0) + bR;                                                              \
        const float* bsrc0 = (kk < NN) ? &Bsrc[(size_t)kk * ncols + n0 + bC] : Bsrc;     \
        int bsz = (kk < NN) ? 16 : 0;                                                    \
        uint32_t bdst = smem_u32(&Bs[s][bR][bC]);                                        \
        cpa16z(bdst, bsrc0, bsz);                                                        \
        cpa16z(bdst + 16u, (kk < NN) ? bsrc0 + 4 : Bsrc, bsz);                           \
        asm volatile("cp.async.commit_group;" ::: "memory");                             \
    } while (0)

    LOAD_STAGE(0, 0);

    for (int i = 0; i < KCH; i++) {
        const int s = i & 1;
        if (i + 1 < KCH) {
            LOAD_STAGE(s ^ 1, (i + 1) * BK);
            asm volatile("cp.async.wait_group 1;" ::: "memory");
        } else {
            asm volatile("cp.async.wait_group 0;" ::: "memory");
        }
        __syncthreads();

#pragma unroll
        for (int ks = 0; ks < 2; ks++) {
            const int kk = ks * 8;
            uint32_t ahi[2][4], alo[2][4];
#pragma unroll
            for (int tm = 0; tm < 2; tm++) {
                int r = wm + tm * 16 + gid;
                split_tf32(As[s][r][kk + tig], ahi[tm][0], alo[tm][0]);
                split_tf32(As[s][r + 8][kk + tig], ahi[tm][1], alo[tm][1]);
                split_tf32(As[s][r][kk + tig + 4], ahi[tm][2], alo[tm][2]);
                split_tf32(As[s][r + 8][kk + tig + 4], ahi[tm][3], alo[tm][3]);
            }
#pragma unroll
            for (int j = 0; j < 8; j++) {
                int col = wn + j * 8 + gid;
                uint32_t bh[2], bl[2];
                split_tf32(Bs[s][kk + tig][col], bh[0], bl[0]);
                split_tf32(Bs[s][kk + tig + 4][col], bh[1], bl[1]);
#pragma unroll
                for (int tm = 0; tm < 2; tm++) {
                    MMA_TF32(acc[tm][j], ahi[tm], bh);
                    MMA_TF32(acc[tm][j], ahi[tm], bl);
                    MMA_TF32(acc[tm][j], alo[tm], bh);
                }
            }
        }
        __syncthreads();
    }

    // epilogue
#pragma unroll
    for (int tm = 0; tm < 2; tm++) {
        int r0 = m0 + wm + tm * 16 + gid;
        int r1 = r0 + 8;
#pragma unroll
        for (int j = 0; j < 8; j++) {
            int col = n0 + wn + j * 8 + 2 * tig;
            if (r0 < NN)
                *(float2*)&C[(size_t)r0 * ncols + col] = make_float2(acc[tm][j][0], acc[tm][j][1]);
            if (r1 < NN)
                *(float2*)&C[(size_t)r1 * ncols + col] = make_float2(acc[tm][j][2], acc[tm][j][3]);
        }
    }
#undef LOAD_STAGE
}

// ---------------- per-node weight materialization: Wn = E[n] . W ----------------
__global__ void prep_gate_kernel(const float* __restrict__ E,
                                 const float* __restrict__ Wf, const float* __restrict__ bf,
                                 const float* __restrict__ Wb, const float* __restrict__ bb) {
    int n = blockIdx.x, dir = blockIdx.y;
    const float* W = dir ? Wb : Wf;
    const float* bsrc = dir ? bb : bf;
    __shared__ float en[DE];
    if (threadIdx.x < DE) en[threadIdx.x] = E[n * DE + threadIdx.x];
    __syncthreads();
    float* Wo = &d_Wgn[((size_t)dir * NN + n) * (KI * 128)];
    for (int e = threadIdx.x; e < KI * 128; e += blockDim.x) {
        float s = 0.f;
#pragma unroll
        for (int d = 0; d < DE; d++) s += en[d] * W[(size_t)d * (KI * 128) + e];
        Wo[e] = s;
    }
    for (int o = threadIdx.x; o < 128; o += blockDim.x) {
        float s = 0.f;
#pragma unroll
        for (int d = 0; d < DE; d++) s += en[d] * bsrc[d * 128 + o];
        d_bgn[((size_t)dir * NN + n) * 128 + o] = s;
    }
}

__global__ void prep_cand_kernel(const float* __restrict__ E,
                                 const float* __restrict__ Wf, const float* __restrict__ bf,
                                 const float* __restrict__ Wb, const float* __restrict__ bb) {
    int n = blockIdx.x, dir = blockIdx.y;
    const float* W = dir ? Wb : Wf;
    const float* bsrc = dir ? bb : bf;
    __shared__ float en[DE];
    if (threadIdx.x < DE) en[threadIdx.x] = E[n * DE + threadIdx.x];
    __syncthreads();
    float* Wo = &d_Wcn[((size_t)dir * NN + n) * (KI * 64)];
    for (int e = threadIdx.x; e < KI * 64; e += blockDim.x) {
        float s = 0.f;
#pragma unroll
        for (int d = 0; d < DE; d++) s += en[d] * W[(size_t)d * (KI * 64) + e];
        Wo[e] = s;
    }
    for (int o = threadIdx.x; o < 64; o += blockDim.x) {
        float s = 0.f;
#pragma unroll
        for (int d = 0; d < DE; d++) s += en[d] * bsrc[d * 64 + o];
        d_bcn[((size_t)dir * NN + n) * 64 + o] = s;
    }
}

__global__ void zero_h_kernel() {
    int idx = blockIdx.x * blockDim.x + threadIdx.x;
    if (idx < NN * HCOLS) d_h[idx] = 0.f;
}

// ---------------- gate: zr = sigmoid(A[64x132] @ Wg_n[132x128] + b); z, r*h ----------------
__global__ void gate_kernel(const float* __restrict__ x, int t) {
    extern __shared__ float sm[];
    float(*As)[133] = (float(*)[133])sm;        // [64][133]
    float* Ws = sm + 64 * 133;                  // [KI][128]
    int n = blockIdx.x, dir = blockIdx.y;
    int t_eff = dir ? (TT - 1 - t) : t;
    int tid = threadIdx.x;

    for (int e = tid; e < 64 * KI; e += 256) {
        int b = e / KI;
        int i = e - b * KI;
        int b2 = dir * 64 + b;
        float v;
        if (i < 2)       v = x[(((size_t)b * TT + t_eff) * NN + n) * 2 + i];
        else if (i < 66) v = d_h[((size_t)n * B2 + b2) * DOUTC + (i - 2)];
        else if (i < 68) v = d_SX[(size_t)n * XCOLS + (t_eff * BB + b) * 2 + (i - 66)];
        else             v = d_Sh[((size_t)n * B2 + b2) * DOUTC + (i - 68)];
        As[b][i] = v;
    }
    {
        const float* Wsrc = &d_Wgn[((size_t)dir * NN + n) * (KI * 128)];
        for (int e = tid; e < KI * 128; e += 256) Ws[e] = Wsrc[e];
    }
    __syncthreads();

    int tx = tid & 15, ty = tid >> 4;
    float acc[4][8];
#pragma unroll
    for (int i = 0; i < 4; i++)
#pragma unroll
        for (int j = 0; j < 8; j++) acc[i][j] = 0.f;

    for (int k = 0; k < KI; k++) {
        float a[4], w[8];
#pragma unroll
        for (int i = 0; i < 4; i++) a[i] = As[ty + 16 * i][k];
#pragma unroll
        for (int j = 0; j < 8; j++) w[j] = Ws[k * 128 + tx + 16 * j];
#pragma unroll
        for (int i = 0; i < 4; i++)
#pragma unroll
            for (int j = 0; j < 8; j++) acc[i][j] += a[i] * w[j];
    }

    const float* bgn = &d_bgn[((size_t)dir * NN + n) * 128];
#pragma unroll
    for (int i = 0; i < 4; i++) {
        int b = ty + 16 * i;
        int b2 = dir * 64 + b;
        size_t hb = ((size_t)n * B2 + b2) * DOUTC;
#pragma unroll
        for (int j = 0; j < 8; j++) {
            int o = tx + 16 * j;
            float v = acc[i][j] + bgn[o];
            float s = 1.f / (1.f + expf(-v));
            if (o < DOUTC) d_z[hb + o] = s;
            else           d_rh[hb + (o - DOUTC)] = s * d_h[hb + (o - DOUTC)];
        }
    }
}

// ---------------- candidate + state update + output write ----------------
__global__ void cand_kernel(const float* __restrict__ x, float* __restrict__ out, int t) {
    extern __shared__ float sm[];
    float(*As)[133] = (float(*)[133])sm;        // [64][133]
    float* Ws = sm + 64 * 133;                  // [KI][64]
    int n = blockIdx.x, dir = blockIdx.y;
    int t_eff = dir ? (TT - 1 - t) : t;
    int tid = threadIdx.x;

    for (int e = tid; e < 64 * KI; e += 256) {
        int b = e / KI;
        int i = e - b * KI;
        int b2 = dir * 64 + b;
        float v;
        if (i < 2)       v = x[(((size_t)b * TT + t_eff) * NN + n) * 2 + i];
        else if (i < 66) v = d_rh[((size_t)n * B2 + b2) * DOUTC + (i - 2)];
        else if (i < 68) v = d_SX[(size_t)n * XCOLS + (t_eff * BB + b) * 2 + (i - 66)];
        else             v = d_Srh[((size_t)n * B2 + b2) * DOUTC + (i - 68)];
        As[b][i] = v;
    }
    {
        const float* Wsrc = &d_Wcn[((size_t)dir * NN + n) * (KI * 64)];
        for (int e = tid; e < KI * 64; e += 256) Ws[e] = Wsrc[e];
    }
    __syncthreads();

    int tx = tid & 15, ty = tid >> 4;
    float acc[4][4];
#pragma unroll
    for (int i = 0; i < 4; i++)
#pragma unroll
        for (int j = 0; j < 4; j++) acc[i][j] = 0.f;

    for (int k = 0; k < KI; k++) {
        float a[4], w[4];
#pragma unroll
        for (int i = 0; i < 4; i++) a[i] = As[ty + 16 * i][k];
#pragma unroll
        for (int j = 0; j < 4; j++) w[j] = Ws[k * 64 + tx + 16 * j];
#pragma unroll
        for (int i = 0; i < 4; i++)
#pragma unroll
            for (int j = 0; j < 4; j++) acc[i][j] += a[i] * w[j];
    }

    const float* bcn = &d_bcn[((size_t)dir * NN + n) * 64];
#pragma unroll
    for (int i = 0; i < 4; i++) {
        int b = ty + 16 * i;
        int b2 = dir * 64 + b;
        size_t hb = ((size_t)n * B2 + b2) * DOUTC;
#pragma unroll
        for (int j = 0; j < 4; j++) {
            int o = tx + 16 * j;
            float hc = tanhf(acc[i][j] + bcn[o]);
            float hold = d_h[hb + o];
            float z = d_z[hb + o];
            float hn = z * hold + (1.f - z) * hc;
            d_h[hb + o] = hn;
            out[(((size_t)b * TT + t) * NN + n) * 128 + dir * DOUTC + o] = hn;
        }
    }
}

// ---------------- launch ----------------
extern "C" void kernel_launch(void* const* d_in, const int* in_sizes, int n_in,
                              void* d_out, int out_size) {
    const float* x    = (const float*)d_in[0];
    const float* adj  = (const float*)d_in[1];
    const float* E    = (const float*)d_in[2];
    const float* Wg_f = (const float*)d_in[3];
    const float* bg_f = (const float*)d_in[4];
    const float* Wc_f = (const float*)d_in[5];
    const float* bc_f = (const float*)d_in[6];
    const float* Wg_b = (const float*)d_in[7];
    const float* bg_b = (const float*)d_in[8];
    const float* Wc_b = (const float*)d_in[9];
    const float* bc_b = (const float*)d_in[10];
    float* out = (float*)d_out;

    const int gate_smem = (64 * 133 + KI * 128) * (int)sizeof(float);
    const int cand_smem = (64 * 133 + KI * 64) * (int)sizeof(float);
    cudaFuncSetAttribute(gate_kernel, cudaFuncAttributeMaxDynamicSharedMemorySize, gate_smem);
    cudaFuncSetAttribute(cand_kernel, cudaFuncAttributeMaxDynamicSharedMemorySize, cand_smem);

    float *p_xr, *p_SX, *p_h, *p_Sh, *p_rh, *p_Srh;
    cudaGetSymbolAddress((void**)&p_xr, d_xr);
    cudaGetSymbolAddress((void**)&p_SX, d_SX);
    cudaGetSymbolAddress((void**)&p_h, d_h);
    cudaGetSymbolAddress((void**)&p_Sh, d_Sh);
    cudaGetSymbolAddress((void**)&p_rh, d_rh);
    cudaGetSymbolAddress((void**)&p_Srh, d_Srh);

    compute_S_kernel<<<KP, 256>>>(E, adj);
    reorder_x_kernel<<<(NN * XCOLS + 255) / 256, 256>>>(x);
    gemm_mma_kernel<<<dim3(XCOLS / 128, 7), 256>>>(p_xr, p_SX, XCOLS);
    prep_gate_kernel<<<dim3(NN, 2), 256>>>(E, Wg_f, bg_f, Wg_b, bg_b);
    prep_cand_kernel<<<dim3(NN, 2), 256>>>(E, Wc_f, bc_f, Wc_b, bc_b);
    zero_h_kernel<<<(NN * HCOLS + 1023) / 1024, 1024>>>();

    for (int t = 0; t < TT; t++) {
        gemm_mma_kernel<<<dim3(HCOLS / 128, 7), 256>>>(p_h, p_Sh, HCOLS);
        gate_kernel<<<dim3(NN, 2), 256, gate_smem>>>(x, t);
        gemm_mma_kernel<<<dim3(HCOLS / 128, 7), 256>>>(p_rh, p_Srh, HCOLS);
        cand_kernel<<<dim3(NN, 2), 256, cand_smem>>>(x, out, t);
    }
}

// round 5
// speedup vs baseline: 1.3687x; 1.1338x over previous
#include <cuda_runtime.h>
#include <math.h>
#include <stdint.h>

// ---------------- problem constants ----------------
#define NN    883          // nodes
#define KP    896          // padded node dim
#define TT    12           // timesteps
#define BB    64           // batch
#define B2    128          // batch * 2 directions
#define DOUTC 64           // hidden dim
#define DE    10           // embedding dim
#define KI    132          // K-dim of per-node GEMMs: 2 (cheb) * 66 (DI)
#define HCOLS 8192         // B2 * DOUTC
#define XCOLS 1536         // TT * BB * 2
#define BK    16
#define KCH   56           // 896 / 16

// ---------------- device scratch (static, no allocs) ----------------
__device__ float d_S[(size_t)KP * KP];          // S = softmax(relu(EE^T)) + adj, zero-padded
__device__ float d_xr[(size_t)NN * XCOLS];      // x reordered: [m][(t*B+b)*2+i]
__device__ float d_SX[(size_t)NN * XCOLS];      // S @ xr
__device__ float d_h[(size_t)NN * HCOLS];       // h state: [n][b2][c]
__device__ float d_Sh[(size_t)NN * HCOLS];      // S @ h
__device__ float d_rh[(size_t)NN * HCOLS];      // r * h
__device__ float d_Srh[(size_t)NN * HCOLS];     // S @ (r*h)
__device__ float d_z[(size_t)NN * HCOLS];       // update gate z
__device__ float d_Wgn[(size_t)2 * NN * KI * 128];
__device__ float d_bgn[(size_t)2 * NN * 128];
__device__ float d_Wcn[(size_t)2 * NN * KI * 64];
__device__ float d_bcn[(size_t)2 * NN * 64];

// ---------------- helpers ----------------
__device__ __forceinline__ uint32_t smem_u32(const void* p) {
    return (uint32_t)__cvta_generic_to_shared(p);
}
__device__ __forceinline__ void cpa16(uint32_t dst, const float* src) {
    asm volatile("cp.async.cg.shared.global [%0], [%1], 16;" :: "r"(dst), "l"(src));
}
__device__ __forceinline__ void cpa16z(uint32_t dst, const float* src, int srcsize) {
    asm volatile("cp.async.cg.shared.global [%0], [%1], 16, %2;"
                 :: "r"(dst), "l"(src), "r"(srcsize));
}
// bf16 truncation 2-way split of two fp32 values, packed as bf16x2 (v0 in low half).
// hi = top-16-bit truncation (exact mask), lo = v - hi (exact), then truncated to bf16.
__device__ __forceinline__ void split_bf16x2(float v0, float v1, uint32_t& hi, uint32_t& lo) {
    uint32_t u0 = __float_as_uint(v0), u1 = __float_as_uint(v1);
    hi = __byte_perm(u0, u1, 0x7632);
    float l0 = v0 - __uint_as_float(u0 & 0xffff0000u);
    float l1 = v1 - __uint_as_float(u1 & 0xffff0000u);
    lo = __byte_perm(__float_as_uint(l0), __float_as_uint(l1), 0x7632);
}
#define MMA_BF16(d, a, b)                                                      \
    asm volatile("mma.sync.aligned.m16n8k16.row.col.f32.bf16.bf16.f32 "        \
                 "{%0,%1,%2,%3}, {%4,%5,%6,%7}, {%8,%9}, {%0,%1,%2,%3};"       \
                 : "+f"((d)[0]), "+f"((d)[1]), "+f"((d)[2]), "+f"((d)[3])       \
                 : "r"((a)[0]), "r"((a)[1]), "r"((a)[2]), "r"((a)[3]),          \
                   "r"((b)[0]), "r"((b)[1]))

// ---------------- kernel: S = softmax(relu(E E^T)) + adj, padded to [KP][KP] ----------------
__global__ void compute_S_kernel(const float* __restrict__ E, const float* __restrict__ adj) {
    __shared__ float sc[NN];
    __shared__ float red[256];
    int n = blockIdx.x;
    int tid = threadIdx.x;
    if (n >= NN) {
        for (int m = tid; m < KP; m += 256) d_S[(size_t)n * KP + m] = 0.f;
        return;
    }
    float en[DE];
#pragma unroll
    for (int d = 0; d < DE; d++) en[d] = E[n * DE + d];
    float lmax = 0.0f;
    for (int m = tid; m < NN; m += 256) {
        float s = 0.f;
#pragma unroll
        for (int d = 0; d < DE; d++) s += en[d] * E[m * DE + d];
        s = fmaxf(s, 0.f);
        sc[m] = s;
        lmax = fmaxf(lmax, s);
    }
    red[tid] = lmax;
    __syncthreads();
    for (int s = 128; s > 0; s >>= 1) {
        if (tid < s) red[tid] = fmaxf(red[tid], red[tid + s]);
        __syncthreads();
    }
    float mx = red[0];
    __syncthreads();
    float lsum = 0.f;
    for (int m = tid; m < NN; m += 256) {
        float e = expf(sc[m] - mx);
        sc[m] = e;
        lsum += e;
    }
    red[tid] = lsum;
    __syncthreads();
    for (int s = 128; s > 0; s >>= 1) {
        if (tid < s) red[tid] += red[tid + s];
        __syncthreads();
    }
    float inv = 1.0f / red[0];
    for (int m = tid; m < KP; m += 256) {
        float v = (m < NN) ? (sc[m] * inv + adj[(size_t)n * NN + m]) : 0.f;
        d_S[(size_t)n * KP + m] = v;
    }
}

// ---------------- kernel: reorder x -> [m][(t*B+b)*2+i] ----------------
__global__ void reorder_x_kernel(const float* __restrict__ x) {
    int idx = blockIdx.x * blockDim.x + threadIdx.x;
    if (idx >= NN * XCOLS) return;
    int m = idx / XCOLS;
    int c = idx - m * XCOLS;
    int i = c & 1;
    int tb = c >> 1;
    int t = tb / BB;
    int b = tb - t * BB;
    d_xr[idx] = x[(((size_t)b * TT + t) * NN + m) * 2 + i];
}

// ---------------- bf16 3-split mma.sync GEMM: C[883 x ncols] = S @ B ----------------
// A = d_S [KP x KP] (zero padded).  B = Bsrc [NN x ncols] row-major (k-major).
// CTA tile 128x128, BK=16, 8 warps as 4(M) x 2(N), warp tile 32x64, m16n8k16.bf16.
__global__ void __launch_bounds__(256)
gemm_mma_kernel(const float* __restrict__ Bsrc, float* __restrict__ C, int ncols) {
    __shared__ float As[2][128][20];   // [stage][m][k], stride 20
    __shared__ float Bs[2][16][132];   // [stage][k][n], stride 132 (conflict-free b-frags)

    const int tid = threadIdx.x;
    const int wid = tid >> 5;
    const int lane = tid & 31;
    const int gid = lane >> 2;   // 0..7
    const int tig = lane & 3;    // 0..3
    const int m0 = blockIdx.y * 128;
    const int n0 = blockIdx.x * 128;
    const int wm = (wid & 3) * 32;
    const int wn = (wid >> 2) * 64;

    float acc[2][8][4];
#pragma unroll
    for (int tm = 0; tm < 2; tm++)
#pragma unroll
        for (int j = 0; j < 8; j++)
#pragma unroll
            for (int q = 0; q < 4; q++) acc[tm][j][q] = 0.f;

    const int aR = tid >> 1;                 // A row 0..127
    const int aC = (tid & 1) * 8;            // A col chunk
    const int bR = tid >> 4;                 // B k-row 0..15
    const int bC = (tid & 15) * 8;           // B col chunk

#define LOAD_STAGE(s, k0)                                                                \
    do {                                                                                 \
        const float* asrc = &d_S[(size_t)(m0 + aR) * KP + (k0) + aC];                    \
        uint32_t adst = smem_u32(&As[s][aR][aC]);                                        \
        cpa16(adst, asrc);                                                               \
        cpa16(adst + 16u, asrc + 4);                                                     \
        int kk = (k0) + bR;                                                              \
        const float* bsrc0 = (kk < NN) ? &Bsrc[(size_t)kk * ncols + n0 + bC] : Bsrc;     \
        int bsz = (kk < NN) ? 16 : 0;                                                    \
        uint32_t bdst = smem_u32(&Bs[s][bR][bC]);                                        \
        cpa16z(bdst, bsrc0, bsz);                                                        \
        cpa16z(bdst + 16u, (kk < NN) ? bsrc0 + 4 : Bsrc, bsz);                           \
        asm volatile("cp.async.commit_group;" ::: "memory");                             \
    } while (0)

    LOAD_STAGE(0, 0);

    for (int i = 0; i < KCH; i++) {
        const int s = i & 1;
        if (i + 1 < KCH) {
            LOAD_STAGE(s ^ 1, (i + 1) * BK);
            asm volatile("cp.async.wait_group 1;" ::: "memory");
        } else {
            asm volatile("cp.async.wait_group 0;" ::: "memory");
        }
        __syncthreads();

        // A fragments (hi/lo) for both 16-row blocks of the 32-row warp tile
        uint32_t ahi[2][4], alo[2][4];
#pragma unroll
        for (int tm = 0; tm < 2; tm++) {
            int r0 = wm + tm * 16 + gid;
            int r1 = r0 + 8;
            float2 v;
            v = *(float2*)&As[s][r0][2 * tig];
            split_bf16x2(v.x, v.y, ahi[tm][0], alo[tm][0]);
            v = *(float2*)&As[s][r1][2 * tig];
            split_bf16x2(v.x, v.y, ahi[tm][1], alo[tm][1]);
            v = *(float2*)&As[s][r0][2 * tig + 8];
            split_bf16x2(v.x, v.y, ahi[tm][2], alo[tm][2]);
            v = *(float2*)&As[s][r1][2 * tig + 8];
            split_bf16x2(v.x, v.y, ahi[tm][3], alo[tm][3]);
        }

#pragma unroll
        for (int j = 0; j < 8; j++) {
            int col = wn + j * 8 + gid;
            float b00 = Bs[s][2 * tig][col];
            float b01 = Bs[s][2 * tig + 1][col];
            float b10 = Bs[s][2 * tig + 8][col];
            float b11 = Bs[s][2 * tig + 9][col];
            uint32_t bh[2], bl[2];
            split_bf16x2(b00, b01, bh[0], bl[0]);
            split_bf16x2(b10, b11, bh[1], bl[1]);
#pragma unroll
            for (int tm = 0; tm < 2; tm++) {
                MMA_BF16(acc[tm][j], ahi[tm], bh);
                MMA_BF16(acc[tm][j], ahi[tm], bl);
                MMA_BF16(acc[tm][j], alo[tm], bh);
            }
        }
        __syncthreads();
    }

    // epilogue (m16n8 accumulator layout: c0,c1 row gid; c2,c3 row gid+8; cols 2tig,2tig+1)
#pragma unroll
    for (int tm = 0; tm < 2; tm++) {
        int r0 = m0 + wm + tm * 16 + gid;
        int r1 = r0 + 8;
#pragma unroll
        for (int j = 0; j < 8; j++) {
            int col = n0 + wn + j * 8 + 2 * tig;
            if (r0 < NN)
                *(float2*)&C[(size_t)r0 * ncols + col] = make_float2(acc[tm][j][0], acc[tm][j][1]);
            if (r1 < NN)
                *(float2*)&C[(size_t)r1 * ncols + col] = make_float2(acc[tm][j][2], acc[tm][j][3]);
        }
    }
#undef LOAD_STAGE
}

// ---------------- per-node weight materialization: Wn = E[n] . W ----------------
__global__ void prep_gate_kernel(const float* __restrict__ E,
                                 const float* __restrict__ Wf, const float* __restrict__ bf,
                                 const float* __restrict__ Wb, const float* __restrict__ bb) {
    int n = blockIdx.x, dir = blockIdx.y;
    const float* W = dir ? Wb : Wf;
    const float* bsrc = dir ? bb : bf;
    __shared__ float en[DE];
    if (threadIdx.x < DE) en[threadIdx.x] = E[n * DE + threadIdx.x];
    __syncthreads();
    float* Wo = &d_Wgn[((size_t)dir * NN + n) * (KI * 128)];
    for (int e = threadIdx.x; e < KI * 128; e += blockDim.x) {
        float s = 0.f;
#pragma unroll
        for (int d = 0; d < DE; d++) s += en[d] * W[(size_t)d * (KI * 128) + e];
        Wo[e] = s;
    }
    for (int o = threadIdx.x; o < 128; o += blockDim.x) {
        float s = 0.f;
#pragma unroll
        for (int d = 0; d < DE; d++) s += en[d] * bsrc[d * 128 + o];
        d_bgn[((size_t)dir * NN + n) * 128 + o] = s;
    }
}

__global__ void prep_cand_kernel(const float* __restrict__ E,
                                 const float* __restrict__ Wf, const float* __restrict__ bf,
                                 const float* __restrict__ Wb, const float* __restrict__ bb) {
    int n = blockIdx.x, dir = blockIdx.y;
    const float* W = dir ? Wb : Wf;
    const float* bsrc = dir ? bb : bf;
    __shared__ float en[DE];
    if (threadIdx.x < DE) en[threadIdx.x] = E[n * DE + threadIdx.x];
    __syncthreads();
    float* Wo = &d_Wcn[((size_t)dir * NN + n) * (KI * 64)];
    for (int e = threadIdx.x; e < KI * 64; e += blockDim.x) {
        float s = 0.f;
#pragma unroll
        for (int d = 0; d < DE; d++) s += en[d] * W[(size_t)d * (KI * 64) + e];
        Wo[e] = s;
    }
    for (int o = threadIdx.x; o < 64; o += blockDim.x) {
        float s = 0.f;
#pragma unroll
        for (int d = 0; d < DE; d++) s += en[d] * bsrc[d * 64 + o];
        d_bcn[((size_t)dir * NN + n) * 64 + o] = s;
    }
}

__global__ void zero_h_kernel() {
    int idx = blockIdx.x * blockDim.x + threadIdx.x;
    if (idx < NN * HCOLS) d_h[idx] = 0.f;
}

// ---------------- gate: zr = sigmoid(A[64x132] @ Wg_n[132x128] + b); z, r*h ----------------
__global__ void gate_kernel(const float* __restrict__ x, int t) {
    extern __shared__ float sm[];
    float(*As)[133] = (float(*)[133])sm;        // [64][133]
    float* Ws = sm + 64 * 133;                  // [KI][128]
    int n = blockIdx.x, dir = blockIdx.y;
    int t_eff = dir ? (TT - 1 - t) : t;
    int tid = threadIdx.x;

    for (int e = tid; e < 64 * KI; e += 256) {
        int b = e / KI;
        int i = e - b * KI;
        int b2 = dir * 64 + b;
        float v;
        if (i < 2)       v = x[(((size_t)b * TT + t_eff) * NN + n) * 2 + i];
        else if (i < 66) v = d_h[((size_t)n * B2 + b2) * DOUTC + (i - 2)];
        else if (i < 68) v = d_SX[(size_t)n * XCOLS + (t_eff * BB + b) * 2 + (i - 66)];
        else             v = d_Sh[((size_t)n * B2 + b2) * DOUTC + (i - 68)];
        As[b][i] = v;
    }
    {
        const float* Wsrc = &d_Wgn[((size_t)dir * NN + n) * (KI * 128)];
        for (int e = tid; e < KI * 128; e += 256) Ws[e] = Wsrc[e];
    }
    __syncthreads();

    int tx = tid & 15, ty = tid >> 4;
    float acc[4][8];
#pragma unroll
    for (int i = 0; i < 4; i++)
#pragma unroll
        for (int j = 0; j < 8; j++) acc[i][j] = 0.f;

    for (int k = 0; k < KI; k++) {
        float a[4], w[8];
#pragma unroll
        for (int i = 0; i < 4; i++) a[i] = As[ty + 16 * i][k];
#pragma unroll
        for (int j = 0; j < 8; j++) w[j] = Ws[k * 128 + tx + 16 * j];
#pragma unroll
        for (int i = 0; i < 4; i++)
#pragma unroll
            for (int j = 0; j < 8; j++) acc[i][j] += a[i] * w[j];
    }

    const float* bgn = &d_bgn[((size_t)dir * NN + n) * 128];
#pragma unroll
    for (int i = 0; i < 4; i++) {
        int b = ty + 16 * i;
        int b2 = dir * 64 + b;
        size_t hb = ((size_t)n * B2 + b2) * DOUTC;
#pragma unroll
        for (int j = 0; j < 8; j++) {
            int o = tx + 16 * j;
            float v = acc[i][j] + bgn[o];
            float s = 1.f / (1.f + expf(-v));
            if (o < DOUTC) d_z[hb + o] = s;
            else           d_rh[hb + (o - DOUTC)] = s * d_h[hb + (o - DOUTC)];
        }
    }
}

// ---------------- candidate + state update + output write ----------------
__global__ void cand_kernel(const float* __restrict__ x, float* __restrict__ out, int t) {
    extern __shared__ float sm[];
    float(*As)[133] = (float(*)[133])sm;        // [64][133]
    float* Ws = sm + 64 * 133;                  // [KI][64]
    int n = blockIdx.x, dir = blockIdx.y;
    int t_eff = dir ? (TT - 1 - t) : t;
    int tid = threadIdx.x;

    for (int e = tid; e < 64 * KI; e += 256) {
        int b = e / KI;
        int i = e - b * KI;
        int b2 = dir * 64 + b;
        float v;
        if (i < 2)       v = x[(((size_t)b * TT + t_eff) * NN + n) * 2 + i];
        else if (i < 66) v = d_rh[((size_t)n * B2 + b2) * DOUTC + (i - 2)];
        else if (i < 68) v = d_SX[(size_t)n * XCOLS + (t_eff * BB + b) * 2 + (i - 66)];
        else             v = d_Srh[((size_t)n * B2 + b2) * DOUTC + (i - 68)];
        As[b][i] = v;
    }
    {
        const float* Wsrc = &d_Wcn[((size_t)dir * NN + n) * (KI * 64)];
        for (int e = tid; e < KI * 64; e += 256) Ws[e] = Wsrc[e];
    }
    __syncthreads();

    int tx = tid & 15, ty = tid >> 4;
    float acc[4][4];
#pragma unroll
    for (int i = 0; i < 4; i++)
#pragma unroll
        for (int j = 0; j < 4; j++) acc[i][j] = 0.f;

    for (int k = 0; k < KI; k++) {
        float a[4], w[4];
#pragma unroll
        for (int i = 0; i < 4; i++) a[i] = As[ty + 16 * i][k];
#pragma unroll
        for (int j = 0; j < 4; j++) w[j] = Ws[k * 64 + tx + 16 * j];
#pragma unroll
        for (int i = 0; i < 4; i++)
#pragma unroll
            for (int j = 0; j < 4; j++) acc[i][j] += a[i] * w[j];
    }

    const float* bcn = &d_bcn[((size_t)dir * NN + n) * 64];
#pragma unroll
    for (int i = 0; i < 4; i++) {
        int b = ty + 16 * i;
        int b2 = dir * 64 + b;
        size_t hb = ((size_t)n * B2 + b2) * DOUTC;
#pragma unroll
        for (int j = 0; j < 4; j++) {
            int o = tx + 16 * j;
            float hc = tanhf(acc[i][j] + bcn[o]);
            float hold = d_h[hb + o];
            float z = d_z[hb + o];
            float hn = z * hold + (1.f - z) * hc;
            d_h[hb + o] = hn;
            out[(((size_t)b * TT + t) * NN + n) * 128 + dir * DOUTC + o] = hn;
        }
    }
}

// ---------------- launch ----------------
extern "C" void kernel_launch(void* const* d_in, const int* in_sizes, int n_in,
                              void* d_out, int out_size) {
    const float* x    = (const float*)d_in[0];
    const float* adj  = (const float*)d_in[1];
    const float* E    = (const float*)d_in[2];
    const float* Wg_f = (const float*)d_in[3];
    const float* bg_f = (const float*)d_in[4];
    const float* Wc_f = (const float*)d_in[5];
    const float* bc_f = (const float*)d_in[6];
    const float* Wg_b = (const float*)d_in[7];
    const float* bg_b = (const float*)d_in[8];
    const float* Wc_b = (const float*)d_in[9];
    const float* bc_b = (const float*)d_in[10];
    float* out = (float*)d_out;

    const int gate_smem = (64 * 133 + KI * 128) * (int)sizeof(float);
    const int cand_smem = (64 * 133 + KI * 64) * (int)sizeof(float);
    cudaFuncSetAttribute(gate_kernel, cudaFuncAttributeMaxDynamicSharedMemorySize, gate_smem);
    cudaFuncSetAttribute(cand_kernel, cudaFuncAttributeMaxDynamicSharedMemorySize, cand_smem);

    float *p_xr, *p_SX, *p_h, *p_Sh, *p_rh, *p_Srh;
    cudaGetSymbolAddress((void**)&p_xr, d_xr);
    cudaGetSymbolAddress((void**)&p_SX, d_SX);
    cudaGetSymbolAddress((void**)&p_h, d_h);
    cudaGetSymbolAddress((void**)&p_Sh, d_Sh);
    cudaGetSymbolAddress((void**)&p_rh, d_rh);
    cudaGetSymbolAddress((void**)&p_Srh, d_Srh);

    // launch order chosen so ncu (-s 5 -c 1) profiles gemm_mma_kernel at index 5
    compute_S_kernel<<<KP, 256>>>(E, adj);                                   // 0
    reorder_x_kernel<<<(NN * XCOLS + 255) / 256, 256>>>(x);                  // 1
    prep_gate_kernel<<<dim3(NN, 2), 256>>>(E, Wg_f, bg_f, Wg_b, bg_b);       // 2
    prep_cand_kernel<<<dim3(NN, 2), 256>>>(E, Wc_f, bc_f, Wc_b, bc_b);       // 3
    zero_h_kernel<<<(NN * HCOLS + 1023) / 1024, 1024>>>();                   // 4
    gemm_mma_kernel<<<dim3(XCOLS / 128, 7), 256>>>(p_xr, p_SX, XCOLS);       // 5 (profiled)

    for (int t = 0; t < TT; t++) {
        gemm_mma_kernel<<<dim3(HCOLS / 128, 7), 256>>>(p_h, p_Sh, HCOLS);
        gate_kernel<<<dim3(NN, 2), 256, gate_smem>>>(x, t);
        gemm_mma_kernel<<<dim3(HCOLS / 128, 7), 256>>>(p_rh, p_Srh, HCOLS);
        cand_kernel<<<dim3(NN, 2), 256, cand_smem>>>(x, out, t);
    }
}